// round 13
// baseline (speedup 1.0000x reference)
#include <cuda_runtime.h>
#include <cuda_bf16.h>
#include <math.h>
#include <stdint.h>

#define T_STEPS 512
#define B_SZ    64
#define DIN     1024
#define DH      1024
#define TBROWS  (T_STEPS * B_SZ)   // 32768

#define NBLK 128
#define NTHR 256

// ---------------- device scratch (static; no allocation allowed) -------------
__device__ float g_X[3ull * TBROWS * DH];            // x@Wih^T + b, per gate
__device__ __nv_bfloat16 g_Ah[(size_t)TBROWS * DIN]; // emb split hi
__device__ __nv_bfloat16 g_Al[(size_t)TBROWS * DIN]; // emb split lo
__device__ __nv_bfloat16 g_Bh[3ull * DH * DIN];      // w_ih split hi (3 gates)
__device__ __nv_bfloat16 g_Bl[3ull * DH * DIN];      // w_ih split lo
__device__ float g_h [B_SZ * DH];                    // hidden state fp32
__device__ float g_u [B_SZ * DH];                    // update gate
// h and r*h stored as bf16 hi/lo words in m16n8k16 A-FRAGMENT layout:
// word index = (((kb*4 + mf)*32 + lane)<<2) + word, kb = n>>4
__device__ uint32_t g_hfh[B_SZ * DH / 2];
__device__ uint32_t g_hfl[B_SZ * DH / 2];
__device__ uint32_t g_rfh[B_SZ * DH / 2];
__device__ uint32_t g_rfl[B_SZ * DH / 2];
__device__ volatile unsigned g_flags[NBLK * 8];
__device__ volatile unsigned g_rel[NBLK * 8];

// ============================================================================
// helpers
// ============================================================================
__device__ __forceinline__ uint32_t smem_to_u32(const void* p) {
    uint32_t a;
    asm("{ .reg .u64 t; cvta.to.shared.u64 t, %1; cvt.u32.u64 %0, t; }"
        : "=r"(a) : "l"(p));
    return a;
}
__device__ __forceinline__ void cp16(uint32_t dst, const void* src) {
    asm volatile("cp.async.cg.shared.global [%0], [%1], 16;"
                 :: "r"(dst), "l"(src));
}
#define CP_COMMIT() asm volatile("cp.async.commit_group;" ::: "memory")
#define CP_WAIT(n)  asm volatile("cp.async.wait_group %0;" :: "n"(n) : "memory")

#define LDSM_X4(r0, r1, r2, r3, addr) \
    asm volatile("ldmatrix.sync.aligned.m8n8.x4.shared.b16 {%0,%1,%2,%3}, [%4];" \
                 : "=r"(r0), "=r"(r1), "=r"(r2), "=r"(r3) : "r"(addr))

#define MMA_BF16(d, a, b) \
    asm volatile("mma.sync.aligned.m16n8k16.row.col.f32.bf16.bf16.f32 " \
                 "{%0,%1,%2,%3}, {%4,%5,%6,%7}, {%8,%9}, {%0,%1,%2,%3};" \
                 : "+f"((d)[0]), "+f"((d)[1]), "+f"((d)[2]), "+f"((d)[3]) \
                 : "r"((a)[0]), "r"((a)[1]), "r"((a)[2]), "r"((a)[3]), \
                   "r"((b)[0]), "r"((b)[1]))

// fragment word index for element pair (m, n2), n2 even
__device__ __forceinline__ uint32_t frag_word(int m, int n2) {
    int kb   = n2 >> 4;
    int mf   = m >> 4;
    int rl   = m & 15;
    int kl   = n2 & 15;
    int lane = (rl & 7) * 4 + ((kl >> 1) & 3);
    int word = (rl >> 3) + ((kl >> 3) << 1);
    return ((((kb * 4) + mf) * 32 + lane) << 2) + word;
}
__device__ __forceinline__ void split2(float a, float b,
                                       uint32_t& hi, uint32_t& lo) {
    __nv_bfloat162 h, l;
    h.x = __float2bfloat16(a); h.y = __float2bfloat16(b);
    l.x = __float2bfloat16(a - __bfloat162float(h.x));
    l.y = __float2bfloat16(b - __bfloat162float(h.y));
    hi = *(uint32_t*)&h; lo = *(uint32_t*)&l;
}

// ============================================================================
// prep_all
// ============================================================================
__device__ __forceinline__ void split4(const float* __restrict__ src,
                                       __nv_bfloat16* __restrict__ dh,
                                       __nv_bfloat16* __restrict__ dl, size_t i) {
    float4 v = *(const float4*)(src + i * 4);
    uint32_t h0, l0, h1, l1;
    split2(v.x, v.y, h0, l0);
    split2(v.z, v.w, h1, l1);
    *(uint32_t*)(dh + i * 4)     = h0;
    *(uint32_t*)(dh + i * 4 + 2) = h1;
    *(uint32_t*)(dl + i * 4)     = l0;
    *(uint32_t*)(dl + i * 4 + 2) = l1;
}

#define E4 ((size_t)TBROWS * DIN / 4)
#define W4 ((size_t)DH * DIN / 4)
#define H4 ((size_t)B_SZ * DH / 4)
#define PREP_TOT (E4 + 3 * W4 + H4)

__global__ void prep_all(const float* __restrict__ emb,
                         const float* __restrict__ wu,
                         const float* __restrict__ wr,
                         const float* __restrict__ wc,
                         const float* __restrict__ hx) {
    size_t i = (size_t)blockIdx.x * 256 + threadIdx.x;
    if (i >= PREP_TOT) return;
    if (i < E4) { split4(emb, g_Ah, g_Al, i); return; }
    i -= E4;
    if (i < W4) { split4(wu, g_Bh, g_Bl, i); return; }
    i -= W4;
    if (i < W4) { split4(wr, g_Bh + (size_t)DH * DIN, g_Bl + (size_t)DH * DIN, i); return; }
    i -= W4;
    if (i < W4) { split4(wc, g_Bh + 2ull * DH * DIN, g_Bl + 2ull * DH * DIN, i); return; }
    i -= W4;
    {
        int m = (int)((i * 4) / DH);
        int n = (int)((i * 4) % DH);
        float4 v = *(const float4*)(hx + i * 4);
        *(float4*)(g_h + i * 4) = v;
        uint32_t h0, l0, h1, l1;
        split2(v.x, v.y, h0, l0);
        split2(v.z, v.w, h1, l1);
        uint32_t f0 = frag_word(m, n), f1 = frag_word(m, n + 2);
        g_hfh[f0] = h0; g_hfh[f1] = h1;
        g_hfl[f0] = l0; g_hfl[f1] = l1;
        if (i < NBLK * 8) { g_flags[i] = 0u; g_rel[i] = 0u; }
    }
}

// ============================================================================
// HMMA input GEMM (unchanged from passing rounds 4-11)
// ============================================================================
#define KT       32
#define NKT      (DIN / KT)
#define TSTRB    80
#define TILE_SB  (128 * TSTRB)
#define STAGE_SB (4 * TILE_SB)
#define GEMM_SM  (2 * STAGE_SB)

__global__ __launch_bounds__(256)
void gemm_input_tc(const float* __restrict__ bu, const float* __restrict__ br,
                   const float* __restrict__ bc) {
    extern __shared__ char smem[];
    const uint32_t sm0 = smem_to_u32(smem);

    const int g  = blockIdx.z;
    const int n0 = blockIdx.x * 128;
    const int m0 = blockIdx.y * 128;
    const float* bias = (g == 0) ? bu : (g == 1) ? br : bc;
    float* X = g_X + (size_t)g * TBROWS * DH;

    const int tid  = threadIdx.x;
    const int lane = tid & 31;
    const int wm   = (tid >> 5) & 3;
    const int wn   = tid >> 7;

    const int p = tid >> 6;
    const int q = tid & 63;
    const __nv_bfloat16* srcb;
    if (p == 0)      srcb = g_Ah + (size_t)(m0 + q) * DIN;
    else if (p == 1) srcb = g_Al + (size_t)(m0 + q) * DIN;
    else if (p == 2) srcb = g_Bh + ((size_t)g * DH + n0 + q) * DIN;
    else             srcb = g_Bl + ((size_t)g * DH + n0 + q) * DIN;
    const uint32_t dstb = sm0 + p * TILE_SB + q * TSTRB;

    float acc[2][8][4];
#pragma unroll
    for (int mf = 0; mf < 2; mf++)
#pragma unroll
        for (int nf = 0; nf < 8; nf++)
#pragma unroll
            for (int e = 0; e < 4; e++) acc[mf][nf][e] = 0.f;

#pragma unroll
    for (int j = 0; j < 4; j++) {
        cp16(dstb + j * 16,               srcb + j * 8);
        cp16(dstb + 64 * TSTRB + j * 16,  srcb + (size_t)64 * DIN + j * 8);
    }
    CP_COMMIT();

    for (int c = 0; c < NKT; c++) {
        const uint32_t sb = sm0 + (c & 1) * STAGE_SB;
        if (c + 1 < NKT) {
            const uint32_t d2 = sm0 + ((c + 1) & 1) * STAGE_SB
                              + p * TILE_SB + q * TSTRB;
            const __nv_bfloat16* s2 = srcb + (c + 1) * KT;
#pragma unroll
            for (int j = 0; j < 4; j++) {
                cp16(d2 + j * 16,              s2 + j * 8);
                cp16(d2 + 64 * TSTRB + j * 16, s2 + (size_t)64 * DIN + j * 8);
            }
            CP_COMMIT();
            CP_WAIT(1);
        } else {
            CP_WAIT(0);
        }
        __syncthreads();

        const uint32_t arow = (lane & 15);
        const uint32_t acol = (lane >> 4) * 16;
#pragma unroll
        for (int s = 0; s < 2; s++) {
            uint32_t ah[2][4], al[2][4], bh[8][2], bl[8][2];
#pragma unroll
            for (int mf = 0; mf < 2; mf++) {
                uint32_t ra = sb + (32 * wm + 16 * mf + arow) * TSTRB + acol + s * 32;
                LDSM_X4(ah[mf][0], ah[mf][1], ah[mf][2], ah[mf][3], ra);
                LDSM_X4(al[mf][0], al[mf][1], al[mf][2], al[mf][3], ra + TILE_SB);
            }
#pragma unroll
            for (int nfp = 0; nfp < 4; nfp++) {
                uint32_t rb = sb + 2 * TILE_SB
                            + (64 * wn + 16 * nfp + arow) * TSTRB + acol + s * 32;
                uint32_t r0, r1, r2, r3;
                LDSM_X4(r0, r1, r2, r3, rb);
                bh[2 * nfp][0] = r0; bh[2 * nfp][1] = r2;
                bh[2 * nfp + 1][0] = r1; bh[2 * nfp + 1][1] = r3;
                LDSM_X4(r0, r1, r2, r3, rb + TILE_SB);
                bl[2 * nfp][0] = r0; bl[2 * nfp][1] = r2;
                bl[2 * nfp + 1][0] = r1; bl[2 * nfp + 1][1] = r3;
            }
#pragma unroll
            for (int mf = 0; mf < 2; mf++)
#pragma unroll
                for (int nf = 0; nf < 8; nf++) {
                    MMA_BF16(acc[mf][nf], ah[mf], bh[nf]);
                    MMA_BF16(acc[mf][nf], ah[mf], bl[nf]);
                    MMA_BF16(acc[mf][nf], al[mf], bh[nf]);
                }
        }
        __syncthreads();
    }

#pragma unroll
    for (int mf = 0; mf < 2; mf++) {
        int row0 = m0 + wm * 32 + mf * 16 + (lane >> 2);
#pragma unroll
        for (int nf = 0; nf < 8; nf++) {
            int col = n0 + wn * 64 + nf * 8 + (lane & 3) * 2;
            float2 bv = *(const float2*)(bias + col);
            float2 o0 = make_float2(acc[mf][nf][0] + bv.x, acc[mf][nf][1] + bv.y);
            float2 o1 = make_float2(acc[mf][nf][2] + bv.x, acc[mf][nf][3] + bv.y);
            *(float2*)(X + (size_t)row0 * DH + col)       = o0;
            *(float2*)(X + (size_t)(row0 + 8) * DH + col) = o1;
        }
    }
}

// ============================================================================
// Atomic-free two-level grid barrier with per-CTA release lines
// ============================================================================
__device__ __forceinline__ void grid_barrier(unsigned& lgen) {
    __threadfence();
    __syncthreads();
    const unsigned target = ++lgen;
    if (threadIdx.x == 0) g_flags[blockIdx.x * 8] = target;
    if (blockIdx.x == 0) {
        if (threadIdx.x < NBLK) {
            while (g_flags[threadIdx.x * 8] < target) { }
        }
        __syncthreads();
        __threadfence();
        if (threadIdx.x < NBLK) g_rel[threadIdx.x * 8] = target;
    }
    if (threadIdx.x == 0) {
        while (g_rel[blockIdx.x * 8] < target) { }
        __threadfence();
    }
    __syncthreads();
}

// ============================================================================
// Persistent tensor-core recurrence.
//  - A-operands: LDG.128 fragments direct from gmem, double-buffered across j
//  - phase-A weights: registers; phase-B weights: persistent smem (LDSM per j)
//  - phase B runs on CTAs [0,64) with 16 cols each (halved chip L2 traffic)
// SMEM: [0, 81920)   phase-A weight staging -> later reduction scratch
//       [81920, 163840) phase-B weights (persistent; hi 40960 + lo 40960)
// ============================================================================
#define WSA_HALF 40960
#define WSB_HALF 40960
#define SM_WSA   0
#define SM_WSB   81920
#define PERS_SM  163840

__global__ __launch_bounds__(NTHR, 1)
void gru_pers_tc(const float* __restrict__ Wu, const float* __restrict__ Wr,
                 const float* __restrict__ Wc, float* __restrict__ out,
                 int write_tail) {
    extern __shared__ char sm[];
    const uint32_t sm0 = smem_to_u32(sm);
    float* red = (float*)sm;              // per-warp 1536-float regions

    const int tid  = threadIdx.x;
    const int wid  = tid >> 5;
    const int lane = tid & 31;
    const int b    = blockIdx.x;
    const int gA   = b >> 6;
    const int n0A  = (b & 63) * 16;
    const int pb   = (b < 64);             // phase-B active CTA
    const int n0B  = b * 16;               // valid when pb
    const float* WA = gA ? Wr : Wu;

    // ---- stage phase-A weights (80B-stride ktile layout), move to regs
    for (int e = tid; e < 16 * 512; e += NTHR) {
        int row = e >> 9, k = (e & 511) * 2;
        float2 v = *(const float2*)(WA + (size_t)(n0A + row) * DH + k);
        uint32_t hw, lw; split2(v.x, v.y, hw, lw);
        uint32_t ad = SM_WSA + (k >> 5) * 1280 + row * 80 + (k & 31) * 2;
        *(uint32_t*)(sm + ad)            = hw;
        *(uint32_t*)(sm + ad + WSA_HALF) = lw;
    }
    // ---- stage phase-B weights into persistent smem (16 rows x 1024 k)
    if (pb) {
        for (int e = tid; e < 16 * 512; e += NTHR) {
            int row = e >> 9, k = (e & 511) * 2;
            float2 v = *(const float2*)(Wc + (size_t)(n0B + row) * DH + k);
            uint32_t hw, lw; split2(v.x, v.y, hw, lw);
            uint32_t ad = SM_WSB + (k >> 5) * 1280 + row * 80 + (k & 31) * 2;
            *(uint32_t*)(sm + ad)            = hw;
            *(uint32_t*)(sm + ad + WSB_HALF) = lw;
        }
    }
    __syncthreads();

    // ---- phase-A weight fragments -> registers (step-invariant)
    uint32_t wAh0[8][2], wAh1[8][2], wAl0[8][2], wAl1[8][2];
#pragma unroll
    for (int j = 0; j < 8; j++) {
        const int kt = 4 * wid + (j >> 1);
        uint32_t bA = sm0 + SM_WSA + kt * 1280
                    + (lane & 15) * 80 + (lane >> 4) * 16 + (j & 1) * 32;
        uint32_t r0, r1, r2, r3;
        LDSM_X4(r0, r1, r2, r3, bA);
        wAh0[j][0] = r0; wAh0[j][1] = r2; wAh1[j][0] = r1; wAh1[j][1] = r3;
        LDSM_X4(r0, r1, r2, r3, bA + WSA_HALF);
        wAl0[j][0] = r0; wAl0[j][1] = r2; wAl1[j][0] = r1; wAl1[j][1] = r3;
    }
    __syncthreads();   // WSA region now reusable as reduction scratch

    const int mE  = tid >> 2;
    const int cbA = (tid & 3) * 4;
    const int nAe = n0A + cbA;
    const int nBe = n0B + cbA;             // phase-B epilogue cols (when pb)
    unsigned lgen = 0;

    float4 hcar = make_float4(0.f, 0.f, 0.f, 0.f);
    if (pb) hcar = *(const float4*)(g_h + mE * DH + nBe);
    float4 xgA = *(const float4*)(g_X + ((size_t)gA * TBROWS) * DH + mE * DH + nAe);

    uint4 bufh[2][4], bufl[2][4];

    for (int t = 0; t < T_STEPS; t++) {
        // ---------------- PHASE A (u, r) ----------------
        float4 hvA = *(const float4*)(g_h + mE * DH + nAe);

        float acc[4][2][4];
#pragma unroll
        for (int mf = 0; mf < 4; mf++)
#pragma unroll
            for (int nf = 0; nf < 2; nf++)
#pragma unroll
                for (int e = 0; e < 4; e++) acc[mf][nf][e] = 0.f;

        {
            const uint4* ph = (const uint4*)(g_hfh + (size_t)(wid * 8) * 512);
            const uint4* pl = (const uint4*)(g_hfl + (size_t)(wid * 8) * 512);
#pragma unroll
            for (int mf = 0; mf < 4; mf++) {
                bufh[0][mf] = ph[mf * 32 + lane];
                bufl[0][mf] = pl[mf * 32 + lane];
            }
        }
#pragma unroll
        for (int j = 0; j < 8; j++) {
            const int cur = j & 1;
            if (j < 7) {
                const uint4* ph = (const uint4*)(g_hfh + (size_t)(wid * 8 + j + 1) * 512);
                const uint4* pl = (const uint4*)(g_hfl + (size_t)(wid * 8 + j + 1) * 512);
#pragma unroll
                for (int mf = 0; mf < 4; mf++) {
                    bufh[cur ^ 1][mf] = ph[mf * 32 + lane];
                    bufl[cur ^ 1][mf] = pl[mf * 32 + lane];
                }
            }
#pragma unroll
            for (int mf = 0; mf < 4; mf++) {
                uint32_t ah[4] = {bufh[cur][mf].x, bufh[cur][mf].y,
                                  bufh[cur][mf].z, bufh[cur][mf].w};
                uint32_t al[4] = {bufl[cur][mf].x, bufl[cur][mf].y,
                                  bufl[cur][mf].z, bufl[cur][mf].w};
                MMA_BF16(acc[mf][0], ah, wAh0[j]);
                MMA_BF16(acc[mf][0], ah, wAl0[j]);
                MMA_BF16(acc[mf][0], al, wAh0[j]);
                MMA_BF16(acc[mf][1], ah, wAh1[j]);
                MMA_BF16(acc[mf][1], ah, wAl1[j]);
                MMA_BF16(acc[mf][1], al, wAh1[j]);
            }
        }

        {
            float* rw = red + wid * 1536;
#pragma unroll
            for (int mf = 0; mf < 4; mf++)
#pragma unroll
                for (int nf = 0; nf < 2; nf++) {
                    int row = mf * 16 + (lane >> 2);
                    int col = nf * 8 + (lane & 3) * 2;
                    *(float2*)&rw[row * 20 + col] =
                        make_float2(acc[mf][nf][0], acc[mf][nf][1]);
                    *(float2*)&rw[(row + 8) * 20 + col] =
                        make_float2(acc[mf][nf][2], acc[mf][nf][3]);
                }
        }
        __syncthreads();
        {
            float4 sv = make_float4(0.f, 0.f, 0.f, 0.f);
#pragma unroll
            for (int w = 0; w < 8; w++) {
                float4 v = *(float4*)&red[w * 1536 + mE * 20 + cbA];
                sv.x += v.x; sv.y += v.y; sv.z += v.z; sv.w += v.w;
            }
            float s0 = 1.f / (1.f + expf(-(sv.x + xgA.x)));
            float s1 = 1.f / (1.f + expf(-(sv.y + xgA.y)));
            float s2 = 1.f / (1.f + expf(-(sv.z + xgA.z)));
            float s3 = 1.f / (1.f + expf(-(sv.w + xgA.w)));
            if (gA == 0) {
                *(float4*)&g_u[mE * DH + nAe] = make_float4(s0, s1, s2, s3);
            } else {
                float r0f = s0 * hvA.x, r1f = s1 * hvA.y;
                float r2f = s2 * hvA.z, r3f = s3 * hvA.w;
                uint32_t h01, l01, h23, l23;
                split2(r0f, r1f, h01, l01);
                split2(r2f, r3f, h23, l23);
                uint32_t f0 = frag_word(mE, nAe), f1 = frag_word(mE, nAe + 2);
                g_rfh[f0] = h01; g_rfh[f1] = h23;
                g_rfl[f0] = l01; g_rfl[f1] = l23;
            }
        }
        float4 xcB = make_float4(0.f, 0.f, 0.f, 0.f);
        if (pb) xcB = *(const float4*)(g_X + (2ull * TBROWS
                          + (size_t)t * B_SZ) * DH + mE * DH + nBe);
        grid_barrier(lgen);

        // ---------------- PHASE B (candidate + update), CTAs [0,64) --------
        if (pb) {
            float4 uvB = *(const float4*)(g_u + mE * DH + nBe);

            float accB[4][2][4];
#pragma unroll
            for (int mf = 0; mf < 4; mf++)
#pragma unroll
                for (int nf = 0; nf < 2; nf++)
#pragma unroll
                    for (int e = 0; e < 4; e++) accB[mf][nf][e] = 0.f;

            {
                const uint4* ph = (const uint4*)(g_rfh + (size_t)(wid * 8) * 512);
                const uint4* pl = (const uint4*)(g_rfl + (size_t)(wid * 8) * 512);
#pragma unroll
                for (int mf = 0; mf < 4; mf++) {
                    bufh[0][mf] = ph[mf * 32 + lane];
                    bufl[0][mf] = pl[mf * 32 + lane];
                }
            }
#pragma unroll
            for (int j = 0; j < 8; j++) {
                const int cur = j & 1;
                if (j < 7) {
                    const uint4* ph = (const uint4*)(g_rfh + (size_t)(wid * 8 + j + 1) * 512);
                    const uint4* pl = (const uint4*)(g_rfl + (size_t)(wid * 8 + j + 1) * 512);
#pragma unroll
                    for (int mf = 0; mf < 4; mf++) {
                        bufh[cur ^ 1][mf] = ph[mf * 32 + lane];
                        bufl[cur ^ 1][mf] = pl[mf * 32 + lane];
                    }
                }
                // weights from persistent smem (same layout as phase A)
                const int kt = 4 * wid + (j >> 1);
                uint32_t bB = sm0 + SM_WSB + kt * 1280
                            + (lane & 15) * 80 + (lane >> 4) * 16 + (j & 1) * 32;
                uint32_t r0, r1, r2, r3;
                uint32_t wh0[2], wh1[2], wl0[2], wl1[2];
                LDSM_X4(r0, r1, r2, r3, bB);
                wh0[0] = r0; wh0[1] = r2; wh1[0] = r1; wh1[1] = r3;
                LDSM_X4(r0, r1, r2, r3, bB + WSB_HALF);
                wl0[0] = r0; wl0[1] = r2; wl1[0] = r1; wl1[1] = r3;
#pragma unroll
                for (int mf = 0; mf < 4; mf++) {
                    uint32_t ah[4] = {bufh[cur][mf].x, bufh[cur][mf].y,
                                      bufh[cur][mf].z, bufh[cur][mf].w};
                    uint32_t al[4] = {bufl[cur][mf].x, bufl[cur][mf].y,
                                      bufl[cur][mf].z, bufl[cur][mf].w};
                    MMA_BF16(accB[mf][0], ah, wh0);
                    MMA_BF16(accB[mf][0], ah, wl0);
                    MMA_BF16(accB[mf][0], al, wh0);
                    MMA_BF16(accB[mf][1], ah, wh1);
                    MMA_BF16(accB[mf][1], ah, wl1);
                    MMA_BF16(accB[mf][1], al, wh1);
                }
            }

            {
                float* rw = red + wid * 1536;
#pragma unroll
                for (int mf = 0; mf < 4; mf++)
#pragma unroll
                    for (int nf = 0; nf < 2; nf++) {
                        int row = mf * 16 + (lane >> 2);
                        int col = nf * 8 + (lane & 3) * 2;
                        *(float2*)&rw[row * 20 + col] =
                            make_float2(accB[mf][nf][0], accB[mf][nf][1]);
                        *(float2*)&rw[(row + 8) * 20 + col] =
                            make_float2(accB[mf][nf][2], accB[mf][nf][3]);
                    }
            }
            __syncthreads();
            {
                float4 sv = make_float4(0.f, 0.f, 0.f, 0.f);
#pragma unroll
                for (int w = 0; w < 8; w++) {
                    float4 v = *(float4*)&red[w * 1536 + mE * 20 + cbA];
                    sv.x += v.x; sv.y += v.y; sv.z += v.z; sv.w += v.w;
                }
                float c0 = tanhf(sv.x + xcB.x);
                float c1 = tanhf(sv.y + xcB.y);
                float c2 = tanhf(sv.z + xcB.z);
                float c3 = tanhf(sv.w + xcB.w);
                float hn0 = (1.f - uvB.x) * hcar.x + uvB.x * c0;
                float hn1 = (1.f - uvB.y) * hcar.y + uvB.y * c1;
                float hn2 = (1.f - uvB.z) * hcar.z + uvB.z * c2;
                float hn3 = (1.f - uvB.w) * hcar.w + uvB.w * c3;
                hcar = make_float4(hn0, hn1, hn2, hn3);
                *(float4*)&g_h[mE * DH + nBe] = hcar;
                uint32_t h01, l01, h23, l23;
                split2(hn0, hn1, h01, l01);
                split2(hn2, hn3, h23, l23);
                uint32_t f0 = frag_word(mE, nBe), f1 = frag_word(mE, nBe + 2);
                g_hfh[f0] = h01; g_hfh[f1] = h23;
                g_hfl[f0] = l01; g_hfl[f1] = l23;
                size_t ob = ((size_t)t * B_SZ + mE) * DH + nBe;
                *(float4*)&out[ob] = hcar;
                if (write_tail && t == T_STEPS - 1) {
                    size_t tb = ((size_t)T_STEPS * B_SZ + mE) * DH + nBe;
                    *(float4*)&out[tb] = hcar;
                }
            }
        }
        if (t + 1 < T_STEPS) {
            xgA = *(const float4*)(g_X + ((size_t)gA * TBROWS
                      + (size_t)(t + 1) * B_SZ) * DH + mE * DH + nAe);
        }
        grid_barrier(lgen);
    }
}

// ============================================================================
// Launch: 3 kernels per call
// ============================================================================
extern "C" void kernel_launch(void* const* d_in, const int* in_sizes, int n_in,
                              void* d_out, int out_size) {
    const float* emb    = (const float*)d_in[0];
    const float* hx     = (const float*)d_in[1];
    const float* w_ih_u = (const float*)d_in[2];
    const float* w_ih_r = (const float*)d_in[3];
    const float* w_ih_c = (const float*)d_in[4];
    const float* w_hh_u = (const float*)d_in[5];
    const float* w_hh_r = (const float*)d_in[6];
    const float* w_hh_c = (const float*)d_in[7];
    const float* b_u    = (const float*)d_in[8];
    const float* b_r    = (const float*)d_in[9];
    const float* b_c    = (const float*)d_in[10];
    float* out = (float*)d_out;

    const long long main_elems = (long long)T_STEPS * B_SZ * DH;
    int write_tail = ((long long)out_size >= main_elems + (long long)B_SZ * DH) ? 1 : 0;

    cudaFuncSetAttribute(gemm_input_tc,
                         cudaFuncAttributeMaxDynamicSharedMemorySize, GEMM_SM);
    cudaFuncSetAttribute(gru_pers_tc,
                         cudaFuncAttributeMaxDynamicSharedMemorySize, PERS_SM);

    int prep_blocks = (int)((PREP_TOT + 255) / 256);
    prep_all<<<prep_blocks, 256>>>(emb, w_ih_u, w_ih_r, w_ih_c, hx);

    dim3 g1(DH / 128, TBROWS / 128, 3);
    gemm_input_tc<<<g1, 256, GEMM_SM>>>(b_u, b_r, b_c);
    gru_pers_tc<<<NBLK, NTHR, PERS_SM>>>(w_hh_u, w_hh_r, w_hh_c, out, write_tail);
}

// round 14
// speedup vs baseline: 1.0582x; 1.0582x over previous
#include <cuda_runtime.h>
#include <cuda_bf16.h>
#include <math.h>
#include <stdint.h>

#define T_STEPS 512
#define B_SZ    64
#define DIN     1024
#define DH      1024
#define TBROWS  (T_STEPS * B_SZ)   // 32768

#define NBLK 128
#define NTHR 256
#define NTHR_R 512                 // recurrence kernel threads (16 warps)

// ---------------- device scratch (static; no allocation allowed) -------------
__device__ float g_X[3ull * TBROWS * DH];            // x@Wih^T + b, per gate
__device__ __nv_bfloat16 g_Ah[(size_t)TBROWS * DIN]; // emb split hi
__device__ __nv_bfloat16 g_Al[(size_t)TBROWS * DIN]; // emb split lo
__device__ __nv_bfloat16 g_Bh[3ull * DH * DIN];      // w_ih split hi (3 gates)
__device__ __nv_bfloat16 g_Bl[3ull * DH * DIN];      // w_ih split lo
__device__ float g_h [B_SZ * DH];                    // hidden state fp32
__device__ float g_u [B_SZ * DH];                    // update gate
// h and r*h stored as bf16 hi/lo words in m16n8k16 A-FRAGMENT layout:
// word index = (((kb*4 + mf)*32 + lane)<<2) + word, kb = n>>4
__device__ uint32_t g_hfh[B_SZ * DH / 2];
__device__ uint32_t g_hfl[B_SZ * DH / 2];
__device__ uint32_t g_rfh[B_SZ * DH / 2];
__device__ uint32_t g_rfl[B_SZ * DH / 2];
__device__ volatile unsigned g_flags[NBLK * 8];
__device__ volatile unsigned g_bar_gen;

// ============================================================================
// helpers
// ============================================================================
__device__ __forceinline__ uint32_t smem_to_u32(const void* p) {
    uint32_t a;
    asm("{ .reg .u64 t; cvta.to.shared.u64 t, %1; cvt.u32.u64 %0, t; }"
        : "=r"(a) : "l"(p));
    return a;
}
__device__ __forceinline__ void cp16(uint32_t dst, const void* src) {
    asm volatile("cp.async.cg.shared.global [%0], [%1], 16;"
                 :: "r"(dst), "l"(src));
}
#define CP_COMMIT() asm volatile("cp.async.commit_group;" ::: "memory")
#define CP_WAIT(n)  asm volatile("cp.async.wait_group %0;" :: "n"(n) : "memory")

#define LDSM_X4(r0, r1, r2, r3, addr) \
    asm volatile("ldmatrix.sync.aligned.m8n8.x4.shared.b16 {%0,%1,%2,%3}, [%4];" \
                 : "=r"(r0), "=r"(r1), "=r"(r2), "=r"(r3) : "r"(addr))

#define MMA_BF16(d, a, b) \
    asm volatile("mma.sync.aligned.m16n8k16.row.col.f32.bf16.bf16.f32 " \
                 "{%0,%1,%2,%3}, {%4,%5,%6,%7}, {%8,%9}, {%0,%1,%2,%3};" \
                 : "+f"((d)[0]), "+f"((d)[1]), "+f"((d)[2]), "+f"((d)[3]) \
                 : "r"((a)[0]), "r"((a)[1]), "r"((a)[2]), "r"((a)[3]), \
                   "r"((b)[0]), "r"((b)[1]))

// fragment word index for element pair (m, n2), n2 even
__device__ __forceinline__ uint32_t frag_word(int m, int n2) {
    int kb   = n2 >> 4;
    int mf   = m >> 4;
    int rl   = m & 15;
    int kl   = n2 & 15;
    int lane = (rl & 7) * 4 + ((kl >> 1) & 3);
    int word = (rl >> 3) + ((kl >> 3) << 1);
    return ((((kb * 4) + mf) * 32 + lane) << 2) + word;
}
__device__ __forceinline__ void split2(float a, float b,
                                       uint32_t& hi, uint32_t& lo) {
    __nv_bfloat162 h, l;
    h.x = __float2bfloat16(a); h.y = __float2bfloat16(b);
    l.x = __float2bfloat16(a - __bfloat162float(h.x));
    l.y = __float2bfloat16(b - __bfloat162float(h.y));
    hi = *(uint32_t*)&h; lo = *(uint32_t*)&l;
}

// ============================================================================
// prep_all
// ============================================================================
__device__ __forceinline__ void split4(const float* __restrict__ src,
                                       __nv_bfloat16* __restrict__ dh,
                                       __nv_bfloat16* __restrict__ dl, size_t i) {
    float4 v = *(const float4*)(src + i * 4);
    uint32_t h0, l0, h1, l1;
    split2(v.x, v.y, h0, l0);
    split2(v.z, v.w, h1, l1);
    *(uint32_t*)(dh + i * 4)     = h0;
    *(uint32_t*)(dh + i * 4 + 2) = h1;
    *(uint32_t*)(dl + i * 4)     = l0;
    *(uint32_t*)(dl + i * 4 + 2) = l1;
}

#define E4 ((size_t)TBROWS * DIN / 4)
#define W4 ((size_t)DH * DIN / 4)
#define H4 ((size_t)B_SZ * DH / 4)
#define PREP_TOT (E4 + 3 * W4 + H4)

__global__ void prep_all(const float* __restrict__ emb,
                         const float* __restrict__ wu,
                         const float* __restrict__ wr,
                         const float* __restrict__ wc,
                         const float* __restrict__ hx) {
    size_t i = (size_t)blockIdx.x * 256 + threadIdx.x;
    if (i >= PREP_TOT) return;
    if (i < E4) { split4(emb, g_Ah, g_Al, i); return; }
    i -= E4;
    if (i < W4) { split4(wu, g_Bh, g_Bl, i); return; }
    i -= W4;
    if (i < W4) { split4(wr, g_Bh + (size_t)DH * DIN, g_Bl + (size_t)DH * DIN, i); return; }
    i -= W4;
    if (i < W4) { split4(wc, g_Bh + 2ull * DH * DIN, g_Bl + 2ull * DH * DIN, i); return; }
    i -= W4;
    {
        int m = (int)((i * 4) / DH);
        int n = (int)((i * 4) % DH);
        float4 v = *(const float4*)(hx + i * 4);
        *(float4*)(g_h + i * 4) = v;
        uint32_t h0, l0, h1, l1;
        split2(v.x, v.y, h0, l0);
        split2(v.z, v.w, h1, l1);
        uint32_t f0 = frag_word(m, n), f1 = frag_word(m, n + 2);
        g_hfh[f0] = h0; g_hfh[f1] = h1;
        g_hfl[f0] = l0; g_hfl[f1] = l1;
        if (i < NBLK * 8) g_flags[i] = 0u;
        if (i == 0) g_bar_gen = 0u;
    }
}

// ============================================================================
// HMMA input GEMM (unchanged from passing rounds 4-11)
// ============================================================================
#define KT       32
#define NKT      (DIN / KT)
#define TSTRB    80
#define TILE_SB  (128 * TSTRB)
#define STAGE_SB (4 * TILE_SB)
#define GEMM_SM  (2 * STAGE_SB)

__global__ __launch_bounds__(256)
void gemm_input_tc(const float* __restrict__ bu, const float* __restrict__ br,
                   const float* __restrict__ bc) {
    extern __shared__ char smem[];
    const uint32_t sm0 = smem_to_u32(smem);

    const int g  = blockIdx.z;
    const int n0 = blockIdx.x * 128;
    const int m0 = blockIdx.y * 128;
    const float* bias = (g == 0) ? bu : (g == 1) ? br : bc;
    float* X = g_X + (size_t)g * TBROWS * DH;

    const int tid  = threadIdx.x;
    const int lane = tid & 31;
    const int wm   = (tid >> 5) & 3;
    const int wn   = tid >> 7;

    const int p = tid >> 6;
    const int q = tid & 63;
    const __nv_bfloat16* srcb;
    if (p == 0)      srcb = g_Ah + (size_t)(m0 + q) * DIN;
    else if (p == 1) srcb = g_Al + (size_t)(m0 + q) * DIN;
    else if (p == 2) srcb = g_Bh + ((size_t)g * DH + n0 + q) * DIN;
    else             srcb = g_Bl + ((size_t)g * DH + n0 + q) * DIN;
    const uint32_t dstb = sm0 + p * TILE_SB + q * TSTRB;

    float acc[2][8][4];
#pragma unroll
    for (int mf = 0; mf < 2; mf++)
#pragma unroll
        for (int nf = 0; nf < 8; nf++)
#pragma unroll
            for (int e = 0; e < 4; e++) acc[mf][nf][e] = 0.f;

#pragma unroll
    for (int j = 0; j < 4; j++) {
        cp16(dstb + j * 16,               srcb + j * 8);
        cp16(dstb + 64 * TSTRB + j * 16,  srcb + (size_t)64 * DIN + j * 8);
    }
    CP_COMMIT();

    for (int c = 0; c < NKT; c++) {
        const uint32_t sb = sm0 + (c & 1) * STAGE_SB;
        if (c + 1 < NKT) {
            const uint32_t d2 = sm0 + ((c + 1) & 1) * STAGE_SB
                              + p * TILE_SB + q * TSTRB;
            const __nv_bfloat16* s2 = srcb + (c + 1) * KT;
#pragma unroll
            for (int j = 0; j < 4; j++) {
                cp16(d2 + j * 16,              s2 + j * 8);
                cp16(d2 + 64 * TSTRB + j * 16, s2 + (size_t)64 * DIN + j * 8);
            }
            CP_COMMIT();
            CP_WAIT(1);
        } else {
            CP_WAIT(0);
        }
        __syncthreads();

        const uint32_t arow = (lane & 15);
        const uint32_t acol = (lane >> 4) * 16;
#pragma unroll
        for (int s = 0; s < 2; s++) {
            uint32_t ah[2][4], al[2][4], bh[8][2], bl[8][2];
#pragma unroll
            for (int mf = 0; mf < 2; mf++) {
                uint32_t ra = sb + (32 * wm + 16 * mf + arow) * TSTRB + acol + s * 32;
                LDSM_X4(ah[mf][0], ah[mf][1], ah[mf][2], ah[mf][3], ra);
                LDSM_X4(al[mf][0], al[mf][1], al[mf][2], al[mf][3], ra + TILE_SB);
            }
#pragma unroll
            for (int nfp = 0; nfp < 4; nfp++) {
                uint32_t rb = sb + 2 * TILE_SB
                            + (64 * wn + 16 * nfp + arow) * TSTRB + acol + s * 32;
                uint32_t r0, r1, r2, r3;
                LDSM_X4(r0, r1, r2, r3, rb);
                bh[2 * nfp][0] = r0; bh[2 * nfp][1] = r2;
                bh[2 * nfp + 1][0] = r1; bh[2 * nfp + 1][1] = r3;
                LDSM_X4(r0, r1, r2, r3, rb + TILE_SB);
                bl[2 * nfp][0] = r0; bl[2 * nfp][1] = r2;
                bl[2 * nfp + 1][0] = r1; bl[2 * nfp + 1][1] = r3;
            }
#pragma unroll
            for (int mf = 0; mf < 2; mf++)
#pragma unroll
                for (int nf = 0; nf < 8; nf++) {
                    MMA_BF16(acc[mf][nf], ah[mf], bh[nf]);
                    MMA_BF16(acc[mf][nf], ah[mf], bl[nf]);
                    MMA_BF16(acc[mf][nf], al[mf], bh[nf]);
                }
        }
        __syncthreads();
    }

#pragma unroll
    for (int mf = 0; mf < 2; mf++) {
        int row0 = m0 + wm * 32 + mf * 16 + (lane >> 2);
#pragma unroll
        for (int nf = 0; nf < 8; nf++) {
            int col = n0 + wn * 64 + nf * 8 + (lane & 3) * 2;
            float2 bv = *(const float2*)(bias + col);
            float2 o0 = make_float2(acc[mf][nf][0] + bv.x, acc[mf][nf][1] + bv.y);
            float2 o1 = make_float2(acc[mf][nf][2] + bv.x, acc[mf][nf][3] + bv.y);
            *(float2*)(X + (size_t)row0 * DH + col)       = o0;
            *(float2*)(X + (size_t)(row0 + 8) * DH + col) = o1;
        }
    }
}

// ============================================================================
// Atomic-free two-level grid barrier (R11 version)
// ============================================================================
__device__ __forceinline__ void grid_barrier(unsigned& lgen) {
    __threadfence();
    __syncthreads();
    const unsigned target = ++lgen;
    if (threadIdx.x == 0) g_flags[blockIdx.x * 8] = target;
    if (blockIdx.x == 0) {
        if (threadIdx.x < NBLK) {
            while (g_flags[threadIdx.x * 8] < target) { }
        }
        __syncthreads();
        if (threadIdx.x == 0) { __threadfence(); g_bar_gen = target; }
    }
    if (threadIdx.x == 0) {
        while (g_bar_gen < target) { }
        __threadfence();
    }
    __syncthreads();
}

// ============================================================================
// Persistent tensor-core recurrence, 512 threads (16 warps, 4/SMSP).
//  - A-operands: LDG.128 fragments direct from gmem
//  - phase-A weights: registers; phase-B weights: smem LDSM per j
//  - warp w owns k in [64w, 64w+64): 4 j-subiters of 16k
//  - reduction: 16 partials; scratch aliases WSA (16 x 1280 floats = 80 KB)
//  - epilogues on threads [0,256) with R11's exact per-thread mapping
// ============================================================================
#define WSA_HALF 40960
#define WSB_HALF 20480
#define SM_WSA   0
#define SM_WSB   81920
#define PERS_SM  122880

__global__ __launch_bounds__(NTHR_R, 1)
void gru_pers_tc(const float* __restrict__ Wu, const float* __restrict__ Wr,
                 const float* __restrict__ Wc, float* __restrict__ out,
                 int write_tail) {
    extern __shared__ char sm[];
    const uint32_t sm0 = smem_to_u32(sm);
    float* red = (float*)sm;              // phase A: 16 x 1280 floats

    const int tid  = threadIdx.x;
    const int wid  = tid >> 5;            // 0..15
    const int lane = tid & 31;
    const int b    = blockIdx.x;
    const int gA   = b >> 6;
    const int n0A  = (b & 63) * 16;
    const int n0B  = b * 8;
    const float* WA = gA ? Wr : Wu;

    // ---- stage phase-A weights (80B-stride ktile layout)
    for (int e = tid; e < 16 * 512; e += NTHR_R) {
        int row = e >> 9, k = (e & 511) * 2;
        float2 v = *(const float2*)(WA + (size_t)(n0A + row) * DH + k);
        uint32_t hw, lw; split2(v.x, v.y, hw, lw);
        uint32_t ad = SM_WSA + (k >> 5) * 1280 + row * 80 + (k & 31) * 2;
        *(uint32_t*)(sm + ad)            = hw;
        *(uint32_t*)(sm + ad + WSA_HALF) = lw;
    }
    // ---- stage phase-B weights (8 rows, 640B per ktile)
    for (int e = tid; e < 8 * 512; e += NTHR_R) {
        int row = e >> 9, k = (e & 511) * 2;
        float2 v = *(const float2*)(Wc + (size_t)(n0B + row) * DH + k);
        uint32_t hw, lw; split2(v.x, v.y, hw, lw);
        uint32_t ad = SM_WSB + (k >> 5) * 640 + row * 80 + (k & 31) * 2;
        *(uint32_t*)(sm + ad)            = hw;
        *(uint32_t*)(sm + ad + WSB_HALF) = lw;
    }
    __syncthreads();

    // ---- phase-A weight fragments -> registers (4 j-subiters per warp)
    uint32_t wAh0[4][2], wAh1[4][2], wAl0[4][2], wAl1[4][2];
#pragma unroll
    for (int j = 0; j < 4; j++) {
        const int kt = 2 * wid + (j >> 1);
        uint32_t bA = sm0 + SM_WSA + kt * 1280
                    + (lane & 15) * 80 + (lane >> 4) * 16 + (j & 1) * 32;
        uint32_t r0, r1, r2, r3;
        LDSM_X4(r0, r1, r2, r3, bA);
        wAh0[j][0] = r0; wAh0[j][1] = r2; wAh1[j][0] = r1; wAh1[j][1] = r3;
        LDSM_X4(r0, r1, r2, r3, bA + WSA_HALF);
        wAl0[j][0] = r0; wAl0[j][1] = r2; wAl1[j][0] = r1; wAl1[j][1] = r3;
    }
    __syncthreads();   // WSA region now reusable as reduction scratch

    const bool ep = (tid < 256);
    const int mE  = tid >> 2;              // valid for ep
    const int cbA = (tid & 3) * 4;
    const int nAe = n0A + cbA;
    const int cbB = (tid & 3) * 2;
    const int nBe = n0B + cbB;
    unsigned lgen = 0;

    float hcar0 = 0.f, hcar1 = 0.f;
    if (ep) { float2 hv = *(const float2*)(g_h + mE * DH + nBe); hcar0 = hv.x; hcar1 = hv.y; }
    float4 xgA = make_float4(0.f, 0.f, 0.f, 0.f);
    if (ep) xgA = *(const float4*)(g_X + ((size_t)gA * TBROWS) * DH + mE * DH + nAe);

    for (int t = 0; t < T_STEPS; t++) {
        // ---------------- PHASE A (u, r) ----------------
        float4 hvA = make_float4(0.f, 0.f, 0.f, 0.f);
        if (ep) hvA = *(const float4*)(g_h + mE * DH + nAe);

        float acc[4][2][4];
#pragma unroll
        for (int mf = 0; mf < 4; mf++)
#pragma unroll
            for (int nf = 0; nf < 2; nf++)
#pragma unroll
                for (int e = 0; e < 4; e++) acc[mf][nf][e] = 0.f;

#pragma unroll
        for (int j = 0; j < 4; j++) {
            const int kb = wid * 4 + j;
            const uint4* ph = (const uint4*)(g_hfh + (size_t)kb * 512);
            const uint4* pl = (const uint4*)(g_hfl + (size_t)kb * 512);
            uint4 ah4[4], al4[4];
#pragma unroll
            for (int mf = 0; mf < 4; mf++) {
                ah4[mf] = ph[mf * 32 + lane];
                al4[mf] = pl[mf * 32 + lane];
            }
#pragma unroll
            for (int mf = 0; mf < 4; mf++) {
                uint32_t ah[4] = {ah4[mf].x, ah4[mf].y, ah4[mf].z, ah4[mf].w};
                uint32_t al[4] = {al4[mf].x, al4[mf].y, al4[mf].z, al4[mf].w};
                MMA_BF16(acc[mf][0], ah, wAh0[j]);
                MMA_BF16(acc[mf][0], ah, wAl0[j]);
                MMA_BF16(acc[mf][0], al, wAh0[j]);
                MMA_BF16(acc[mf][1], ah, wAh1[j]);
                MMA_BF16(acc[mf][1], ah, wAl1[j]);
                MMA_BF16(acc[mf][1], al, wAh1[j]);
            }
        }

        {
            float* rw = red + wid * 1280;
#pragma unroll
            for (int mf = 0; mf < 4; mf++)
#pragma unroll
                for (int nf = 0; nf < 2; nf++) {
                    int row = mf * 16 + (lane >> 2);
                    int col = nf * 8 + (lane & 3) * 2;
                    *(float2*)&rw[row * 20 + col] =
                        make_float2(acc[mf][nf][0], acc[mf][nf][1]);
                    *(float2*)&rw[(row + 8) * 20 + col] =
                        make_float2(acc[mf][nf][2], acc[mf][nf][3]);
                }
        }
        __syncthreads();
        if (ep) {
            float4 sv = make_float4(0.f, 0.f, 0.f, 0.f);
#pragma unroll
            for (int w = 0; w < 16; w++) {
                float4 v = *(float4*)&red[w * 1280 + mE * 20 + cbA];
                sv.x += v.x; sv.y += v.y; sv.z += v.z; sv.w += v.w;
            }
            float s0 = 1.f / (1.f + expf(-(sv.x + xgA.x)));
            float s1 = 1.f / (1.f + expf(-(sv.y + xgA.y)));
            float s2 = 1.f / (1.f + expf(-(sv.z + xgA.z)));
            float s3 = 1.f / (1.f + expf(-(sv.w + xgA.w)));
            if (gA == 0) {
                *(float4*)&g_u[mE * DH + nAe] = make_float4(s0, s1, s2, s3);
            } else {
                float r0f = s0 * hvA.x, r1f = s1 * hvA.y;
                float r2f = s2 * hvA.z, r3f = s3 * hvA.w;
                uint32_t h01, l01, h23, l23;
                split2(r0f, r1f, h01, l01);
                split2(r2f, r3f, h23, l23);
                uint32_t f0 = frag_word(mE, nAe), f1 = frag_word(mE, nAe + 2);
                g_rfh[f0] = h01; g_rfh[f1] = h23;
                g_rfl[f0] = l01; g_rfl[f1] = l23;
            }
        }
        float2 xcB = make_float2(0.f, 0.f);
        if (ep) xcB = *(const float2*)(g_X + (2ull * TBROWS
                          + (size_t)t * B_SZ) * DH + mE * DH + nBe);
        grid_barrier(lgen);

        // ---------------- PHASE B (candidate + update) ----------------
        float2 uvB = make_float2(0.f, 0.f);
        if (ep) uvB = *(const float2*)(g_u + mE * DH + nBe);

        float accB[4][4];
#pragma unroll
        for (int mf = 0; mf < 4; mf++)
#pragma unroll
            for (int e = 0; e < 4; e++) accB[mf][e] = 0.f;

#pragma unroll
        for (int j = 0; j < 4; j++) {
            const int kb = wid * 4 + j;
            const uint4* ph = (const uint4*)(g_rfh + (size_t)kb * 512);
            const uint4* pl = (const uint4*)(g_rfl + (size_t)kb * 512);
            uint4 ah4[4], al4[4];
#pragma unroll
            for (int mf = 0; mf < 4; mf++) {
                ah4[mf] = ph[mf * 32 + lane];
                al4[mf] = pl[mf * 32 + lane];
            }
            // phase-B weights from smem (R11 extraction, new kt formula)
            const int kt = 2 * wid + (j >> 1);
            const int s  = j & 1;
            uint32_t bB = sm0 + SM_WSB + kt * 640
                        + (lane & 7) * 80 + (lane >> 3) * 16;
            uint32_t r0, r1, r2, r3;
            uint32_t bh[2], bl[2];
            LDSM_X4(r0, r1, r2, r3, bB);
            if (s == 0) { bh[0] = r0; bh[1] = r1; } else { bh[0] = r2; bh[1] = r3; }
            LDSM_X4(r0, r1, r2, r3, bB + WSB_HALF);
            if (s == 0) { bl[0] = r0; bl[1] = r1; } else { bl[0] = r2; bl[1] = r3; }
#pragma unroll
            for (int mf = 0; mf < 4; mf++) {
                uint32_t ah[4] = {ah4[mf].x, ah4[mf].y, ah4[mf].z, ah4[mf].w};
                uint32_t al[4] = {al4[mf].x, al4[mf].y, al4[mf].z, al4[mf].w};
                MMA_BF16(accB[mf], ah, bh);
                MMA_BF16(accB[mf], ah, bl);
                MMA_BF16(accB[mf], al, bh);
            }
        }

        {
            float* rw = red + wid * 640;
#pragma unroll
            for (int mf = 0; mf < 4; mf++) {
                int row = mf * 16 + (lane >> 2);
                int col = (lane & 3) * 2;
                *(float2*)&rw[row * 10 + col] =
                    make_float2(accB[mf][0], accB[mf][1]);
                *(float2*)&rw[(row + 8) * 10 + col] =
                    make_float2(accB[mf][2], accB[mf][3]);
            }
        }
        __syncthreads();
        if (ep) {
            float2 sv = make_float2(0.f, 0.f);
#pragma unroll
            for (int w = 0; w < 16; w++) {
                float2 v = *(float2*)&red[w * 640 + mE * 10 + cbB];
                sv.x += v.x; sv.y += v.y;
            }
            float c0 = tanhf(sv.x + xcB.x);
            float c1 = tanhf(sv.y + xcB.y);
            float hn0 = (1.f - uvB.x) * hcar0 + uvB.x * c0;
            float hn1 = (1.f - uvB.y) * hcar1 + uvB.y * c1;
            hcar0 = hn0; hcar1 = hn1;
            *(float2*)&g_h[mE * DH + nBe] = make_float2(hn0, hn1);
            uint32_t hw, lw; split2(hn0, hn1, hw, lw);
            uint32_t f = frag_word(mE, nBe);
            g_hfh[f] = hw; g_hfl[f] = lw;
            size_t ob = ((size_t)t * B_SZ + mE) * DH + nBe;
            *(float2*)&out[ob] = make_float2(hn0, hn1);
            if (write_tail && t == T_STEPS - 1) {
                size_t tb = ((size_t)T_STEPS * B_SZ + mE) * DH + nBe;
                *(float2*)&out[tb] = make_float2(hn0, hn1);
            }
        }
        if (ep && t + 1 < T_STEPS) {
            xgA = *(const float4*)(g_X + ((size_t)gA * TBROWS
                      + (size_t)(t + 1) * B_SZ) * DH + mE * DH + nAe);
        }
        grid_barrier(lgen);
    }
}

// ============================================================================
// Launch: 3 kernels per call
// ============================================================================
extern "C" void kernel_launch(void* const* d_in, const int* in_sizes, int n_in,
                              void* d_out, int out_size) {
    const float* emb    = (const float*)d_in[0];
    const float* hx     = (const float*)d_in[1];
    const float* w_ih_u = (const float*)d_in[2];
    const float* w_ih_r = (const float*)d_in[3];
    const float* w_ih_c = (const float*)d_in[4];
    const float* w_hh_u = (const float*)d_in[5];
    const float* w_hh_r = (const float*)d_in[6];
    const float* w_hh_c = (const float*)d_in[7];
    const float* b_u    = (const float*)d_in[8];
    const float* b_r    = (const float*)d_in[9];
    const float* b_c    = (const float*)d_in[10];
    float* out = (float*)d_out;

    const long long main_elems = (long long)T_STEPS * B_SZ * DH;
    int write_tail = ((long long)out_size >= main_elems + (long long)B_SZ * DH) ? 1 : 0;

    cudaFuncSetAttribute(gemm_input_tc,
                         cudaFuncAttributeMaxDynamicSharedMemorySize, GEMM_SM);
    cudaFuncSetAttribute(gru_pers_tc,
                         cudaFuncAttributeMaxDynamicSharedMemorySize, PERS_SM);

    int prep_blocks = (int)((PREP_TOT + 255) / 256);
    prep_all<<<prep_blocks, 256>>>(emb, w_ih_u, w_ih_r, w_ih_c, hx);

    dim3 g1(DH / 128, TBROWS / 128, 3);
    gemm_input_tc<<<g1, 256, GEMM_SM>>>(b_u, b_r, b_c);
    gru_pers_tc<<<NBLK, NTHR_R, PERS_SM>>>(w_hh_u, w_hh_r, w_hh_c, out, write_tail);
}

// round 15
// speedup vs baseline: 1.0817x; 1.0223x over previous
#include <cuda_runtime.h>
#include <cuda_bf16.h>
#include <math.h>
#include <stdint.h>

#define T_STEPS 512
#define B_SZ    64
#define DIN     1024
#define DH      1024
#define TBROWS  (T_STEPS * B_SZ)   // 32768

#define NBLK 128
#define NTHR 256

// ---------------- device scratch (static; no allocation allowed) -------------
__device__ float g_X[3ull * TBROWS * DH];            // x@Wih^T + b, per gate
__device__ __nv_bfloat16 g_Ah[(size_t)TBROWS * DIN]; // emb split hi
__device__ __nv_bfloat16 g_Al[(size_t)TBROWS * DIN]; // emb split lo
__device__ __nv_bfloat16 g_Bh[3ull * DH * DIN];      // w_ih split hi (3 gates)
__device__ __nv_bfloat16 g_Bl[3ull * DH * DIN];      // w_ih split lo
__device__ float g_h [B_SZ * DH];                    // hidden state fp32
__device__ float g_u [B_SZ * DH];                    // update gate
// h and r*h stored as bf16 hi/lo words in m16n8k16 A-FRAGMENT layout:
// word index = (((kb*4 + mf)*32 + lane)<<2) + word, kb = n>>4
__device__ uint32_t g_hfh[B_SZ * DH / 2];
__device__ uint32_t g_hfl[B_SZ * DH / 2];
__device__ uint32_t g_rfh[B_SZ * DH / 2];
__device__ uint32_t g_rfl[B_SZ * DH / 2];
__device__ volatile unsigned g_flags[NBLK * 8];
__device__ volatile unsigned g_bar_gen;

// ============================================================================
// helpers
// ============================================================================
__device__ __forceinline__ uint32_t smem_to_u32(const void* p) {
    uint32_t a;
    asm("{ .reg .u64 t; cvta.to.shared.u64 t, %1; cvt.u32.u64 %0, t; }"
        : "=r"(a) : "l"(p));
    return a;
}
__device__ __forceinline__ void cp16(uint32_t dst, const void* src) {
    asm volatile("cp.async.cg.shared.global [%0], [%1], 16;"
                 :: "r"(dst), "l"(src));
}
#define CP_COMMIT() asm volatile("cp.async.commit_group;" ::: "memory")
#define CP_WAIT(n)  asm volatile("cp.async.wait_group %0;" :: "n"(n) : "memory")

#define LDSM_X4(r0, r1, r2, r3, addr) \
    asm volatile("ldmatrix.sync.aligned.m8n8.x4.shared.b16 {%0,%1,%2,%3}, [%4];" \
                 : "=r"(r0), "=r"(r1), "=r"(r2), "=r"(r3) : "r"(addr))

#define MMA_BF16(d, a, b) \
    asm volatile("mma.sync.aligned.m16n8k16.row.col.f32.bf16.bf16.f32 " \
                 "{%0,%1,%2,%3}, {%4,%5,%6,%7}, {%8,%9}, {%0,%1,%2,%3};" \
                 : "+f"((d)[0]), "+f"((d)[1]), "+f"((d)[2]), "+f"((d)[3]) \
                 : "r"((a)[0]), "r"((a)[1]), "r"((a)[2]), "r"((a)[3]), \
                   "r"((b)[0]), "r"((b)[1]))

// fragment word index for element pair (m, n2), n2 even
__device__ __forceinline__ uint32_t frag_word(int m, int n2) {
    int kb   = n2 >> 4;
    int mf   = m >> 4;
    int rl   = m & 15;
    int kl   = n2 & 15;
    int lane = (rl & 7) * 4 + ((kl >> 1) & 3);
    int word = (rl >> 3) + ((kl >> 3) << 1);
    return ((((kb * 4) + mf) * 32 + lane) << 2) + word;
}
__device__ __forceinline__ void split2(float a, float b,
                                       uint32_t& hi, uint32_t& lo) {
    __nv_bfloat162 h, l;
    h.x = __float2bfloat16(a); h.y = __float2bfloat16(b);
    l.x = __float2bfloat16(a - __bfloat162float(h.x));
    l.y = __float2bfloat16(b - __bfloat162float(h.y));
    hi = *(uint32_t*)&h; lo = *(uint32_t*)&l;
}

// ============================================================================
// prep_all
// ============================================================================
__device__ __forceinline__ void split4(const float* __restrict__ src,
                                       __nv_bfloat16* __restrict__ dh,
                                       __nv_bfloat16* __restrict__ dl, size_t i) {
    float4 v = *(const float4*)(src + i * 4);
    uint32_t h0, l0, h1, l1;
    split2(v.x, v.y, h0, l0);
    split2(v.z, v.w, h1, l1);
    *(uint32_t*)(dh + i * 4)     = h0;
    *(uint32_t*)(dh + i * 4 + 2) = h1;
    *(uint32_t*)(dl + i * 4)     = l0;
    *(uint32_t*)(dl + i * 4 + 2) = l1;
}

#define E4 ((size_t)TBROWS * DIN / 4)
#define W4 ((size_t)DH * DIN / 4)
#define H4 ((size_t)B_SZ * DH / 4)
#define PREP_TOT (E4 + 3 * W4 + H4)

__global__ void prep_all(const float* __restrict__ emb,
                         const float* __restrict__ wu,
                         const float* __restrict__ wr,
                         const float* __restrict__ wc,
                         const float* __restrict__ hx) {
    size_t i = (size_t)blockIdx.x * 256 + threadIdx.x;
    if (i >= PREP_TOT) return;
    if (i < E4) { split4(emb, g_Ah, g_Al, i); return; }
    i -= E4;
    if (i < W4) { split4(wu, g_Bh, g_Bl, i); return; }
    i -= W4;
    if (i < W4) { split4(wr, g_Bh + (size_t)DH * DIN, g_Bl + (size_t)DH * DIN, i); return; }
    i -= W4;
    if (i < W4) { split4(wc, g_Bh + 2ull * DH * DIN, g_Bl + 2ull * DH * DIN, i); return; }
    i -= W4;
    {
        int m = (int)((i * 4) / DH);
        int n = (int)((i * 4) % DH);
        float4 v = *(const float4*)(hx + i * 4);
        *(float4*)(g_h + i * 4) = v;
        uint32_t h0, l0, h1, l1;
        split2(v.x, v.y, h0, l0);
        split2(v.z, v.w, h1, l1);
        uint32_t f0 = frag_word(m, n), f1 = frag_word(m, n + 2);
        g_hfh[f0] = h0; g_hfh[f1] = h1;
        g_hfl[f0] = l0; g_hfl[f1] = l1;
        if (i < NBLK * 8) g_flags[i] = 0u;
        if (i == 0) g_bar_gen = 0u;
    }
}

// ============================================================================
// HMMA input GEMM (unchanged from passing rounds 4-11)
// ============================================================================
#define KT       32
#define NKT      (DIN / KT)
#define TSTRB    80
#define TILE_SB  (128 * TSTRB)
#define STAGE_SB (4 * TILE_SB)
#define GEMM_SM  (2 * STAGE_SB)

__global__ __launch_bounds__(256)
void gemm_input_tc(const float* __restrict__ bu, const float* __restrict__ br,
                   const float* __restrict__ bc) {
    extern __shared__ char smem[];
    const uint32_t sm0 = smem_to_u32(smem);

    const int g  = blockIdx.z;
    const int n0 = blockIdx.x * 128;
    const int m0 = blockIdx.y * 128;
    const float* bias = (g == 0) ? bu : (g == 1) ? br : bc;
    float* X = g_X + (size_t)g * TBROWS * DH;

    const int tid  = threadIdx.x;
    const int lane = tid & 31;
    const int wm   = (tid >> 5) & 3;
    const int wn   = tid >> 7;

    const int p = tid >> 6;
    const int q = tid & 63;
    const __nv_bfloat16* srcb;
    if (p == 0)      srcb = g_Ah + (size_t)(m0 + q) * DIN;
    else if (p == 1) srcb = g_Al + (size_t)(m0 + q) * DIN;
    else if (p == 2) srcb = g_Bh + ((size_t)g * DH + n0 + q) * DIN;
    else             srcb = g_Bl + ((size_t)g * DH + n0 + q) * DIN;
    const uint32_t dstb = sm0 + p * TILE_SB + q * TSTRB;

    float acc[2][8][4];
#pragma unroll
    for (int mf = 0; mf < 2; mf++)
#pragma unroll
        for (int nf = 0; nf < 8; nf++)
#pragma unroll
            for (int e = 0; e < 4; e++) acc[mf][nf][e] = 0.f;

#pragma unroll
    for (int j = 0; j < 4; j++) {
        cp16(dstb + j * 16,               srcb + j * 8);
        cp16(dstb + 64 * TSTRB + j * 16,  srcb + (size_t)64 * DIN + j * 8);
    }
    CP_COMMIT();

    for (int c = 0; c < NKT; c++) {
        const uint32_t sb = sm0 + (c & 1) * STAGE_SB;
        if (c + 1 < NKT) {
            const uint32_t d2 = sm0 + ((c + 1) & 1) * STAGE_SB
                              + p * TILE_SB + q * TSTRB;
            const __nv_bfloat16* s2 = srcb + (c + 1) * KT;
#pragma unroll
            for (int j = 0; j < 4; j++) {
                cp16(d2 + j * 16,              s2 + j * 8);
                cp16(d2 + 64 * TSTRB + j * 16, s2 + (size_t)64 * DIN + j * 8);
            }
            CP_COMMIT();
            CP_WAIT(1);
        } else {
            CP_WAIT(0);
        }
        __syncthreads();

        const uint32_t arow = (lane & 15);
        const uint32_t acol = (lane >> 4) * 16;
#pragma unroll
        for (int s = 0; s < 2; s++) {
            uint32_t ah[2][4], al[2][4], bh[8][2], bl[8][2];
#pragma unroll
            for (int mf = 0; mf < 2; mf++) {
                uint32_t ra = sb + (32 * wm + 16 * mf + arow) * TSTRB + acol + s * 32;
                LDSM_X4(ah[mf][0], ah[mf][1], ah[mf][2], ah[mf][3], ra);
                LDSM_X4(al[mf][0], al[mf][1], al[mf][2], al[mf][3], ra + TILE_SB);
            }
#pragma unroll
            for (int nfp = 0; nfp < 4; nfp++) {
                uint32_t rb = sb + 2 * TILE_SB
                            + (64 * wn + 16 * nfp + arow) * TSTRB + acol + s * 32;
                uint32_t r0, r1, r2, r3;
                LDSM_X4(r0, r1, r2, r3, rb);
                bh[2 * nfp][0] = r0; bh[2 * nfp][1] = r2;
                bh[2 * nfp + 1][0] = r1; bh[2 * nfp + 1][1] = r3;
                LDSM_X4(r0, r1, r2, r3, rb + TILE_SB);
                bl[2 * nfp][0] = r0; bl[2 * nfp][1] = r2;
                bl[2 * nfp + 1][0] = r1; bl[2 * nfp + 1][1] = r3;
            }
#pragma unroll
            for (int mf = 0; mf < 2; mf++)
#pragma unroll
                for (int nf = 0; nf < 8; nf++) {
                    MMA_BF16(acc[mf][nf], ah[mf], bh[nf]);
                    MMA_BF16(acc[mf][nf], ah[mf], bl[nf]);
                    MMA_BF16(acc[mf][nf], al[mf], bh[nf]);
                }
        }
        __syncthreads();
    }

#pragma unroll
    for (int mf = 0; mf < 2; mf++) {
        int row0 = m0 + wm * 32 + mf * 16 + (lane >> 2);
#pragma unroll
        for (int nf = 0; nf < 8; nf++) {
            int col = n0 + wn * 64 + nf * 8 + (lane & 3) * 2;
            float2 bv = *(const float2*)(bias + col);
            float2 o0 = make_float2(acc[mf][nf][0] + bv.x, acc[mf][nf][1] + bv.y);
            float2 o1 = make_float2(acc[mf][nf][2] + bv.x, acc[mf][nf][3] + bv.y);
            *(float2*)(X + (size_t)row0 * DH + col)       = o0;
            *(float2*)(X + (size_t)(row0 + 8) * DH + col) = o1;
        }
    }
}

// ============================================================================
// Atomic-free two-level grid barrier (tid0-only fences; R8-validated pattern)
// ============================================================================
__device__ __forceinline__ void grid_barrier(unsigned& lgen) {
    __syncthreads();
    const unsigned target = ++lgen;
    if (threadIdx.x == 0) {
        __threadfence();
        g_flags[blockIdx.x * 8] = target;
    }
    if (blockIdx.x == 0) {
        if (threadIdx.x < NBLK) {
            while (g_flags[threadIdx.x * 8] < target) { }
        }
        __syncthreads();
        if (threadIdx.x == 0) { __threadfence(); g_bar_gen = target; }
    }
    if (threadIdx.x == 0) {
        while (g_bar_gen < target) { }
        __threadfence();
    }
    __syncthreads();
}

// ============================================================================
// Persistent tensor-core recurrence (R11 base).
//  - A-operands: LDG.128 fragments direct from gmem in MMA layout
//  - phase-A AND phase-B weights register-resident (B extraction = R10-fused)
// SMEM: [0,122880) weight staging (one-time), then reduction scratch.
// ============================================================================
#define WSA_HALF 40960
#define WSB_HALF 20480
#define SM_WSA   0
#define SM_WSB   81920
#define PERS_SM  122880

__global__ __launch_bounds__(NTHR, 1)
void gru_pers_tc(const float* __restrict__ Wu, const float* __restrict__ Wr,
                 const float* __restrict__ Wc, float* __restrict__ out,
                 int write_tail) {
    extern __shared__ char sm[];
    const uint32_t sm0 = smem_to_u32(sm);
    float* red = (float*)sm;              // per-warp 1536-float regions

    const int tid  = threadIdx.x;
    const int wid  = tid >> 5;
    const int lane = tid & 31;
    const int b    = blockIdx.x;
    const int gA   = b >> 6;
    const int n0A  = (b & 63) * 16;
    const int n0B  = b * 8;
    const float* WA = gA ? Wr : Wu;

    // ---- one-time: split W_hh slices into smem (80B-stride ktile layout)
    for (int e = tid; e < 16 * 512; e += NTHR) {
        int row = e >> 9, k = (e & 511) * 2;
        float2 v = *(const float2*)(WA + (size_t)(n0A + row) * DH + k);
        uint32_t hw, lw; split2(v.x, v.y, hw, lw);
        uint32_t ad = SM_WSA + (k >> 5) * 1280 + row * 80 + (k & 31) * 2;
        *(uint32_t*)(sm + ad)            = hw;
        *(uint32_t*)(sm + ad + WSA_HALF) = lw;
    }
    for (int e = tid; e < 8 * 512; e += NTHR) {
        int row = e >> 9, k = (e & 511) * 2;
        float2 v = *(const float2*)(Wc + (size_t)(n0B + row) * DH + k);
        uint32_t hw, lw; split2(v.x, v.y, hw, lw);
        uint32_t ad = SM_WSB + (k >> 5) * 640 + row * 80 + (k & 31) * 2;
        *(uint32_t*)(sm + ad)            = hw;
        *(uint32_t*)(sm + ad + WSB_HALF) = lw;
    }
    __syncthreads();

    // ---- phase-A weight fragments -> registers (step-invariant)
    uint32_t wAh0[8][2], wAh1[8][2], wAl0[8][2], wAl1[8][2];
#pragma unroll
    for (int j = 0; j < 8; j++) {
        const int kt = 4 * wid + (j >> 1);
        uint32_t bA = sm0 + SM_WSA + kt * 1280
                    + (lane & 15) * 80 + (lane >> 4) * 16 + (j & 1) * 32;
        uint32_t r0, r1, r2, r3;
        LDSM_X4(r0, r1, r2, r3, bA);
        wAh0[j][0] = r0; wAh0[j][1] = r2; wAh1[j][0] = r1; wAh1[j][1] = r3;
        LDSM_X4(r0, r1, r2, r3, bA + WSA_HALF);
        wAl0[j][0] = r0; wAl0[j][1] = r2; wAl1[j][0] = r1; wAl1[j][1] = r3;
    }
    // ---- phase-B weight fragments -> registers (R10-fused validated mapping)
    uint32_t wBh[8][2], wBl[8][2];
#pragma unroll
    for (int i = 0; i < 4; i++) {
        const int kt = 4 * wid + i;
        uint32_t bB = sm0 + SM_WSB + kt * 640
                    + (lane & 7) * 80 + (lane >> 3) * 16;
        uint32_t r0, r1, r2, r3;
        LDSM_X4(r0, r1, r2, r3, bB);
        wBh[2*i][0] = r0; wBh[2*i][1] = r1; wBh[2*i+1][0] = r2; wBh[2*i+1][1] = r3;
        LDSM_X4(r0, r1, r2, r3, bB + WSB_HALF);
        wBl[2*i][0] = r0; wBl[2*i][1] = r1; wBl[2*i+1][0] = r2; wBl[2*i+1][1] = r3;
    }
    __syncthreads();   // weight smem now reusable as reduction scratch

    const int mE  = tid >> 2;
    const int cbA = (tid & 3) * 4;
    const int nAe = n0A + cbA;
    const int cbB = (tid & 3) * 2;
    const int nBe = n0B + cbB;
    unsigned lgen = 0;

    float hcar0, hcar1;
    { float2 hv = *(const float2*)(g_h + mE * DH + nBe); hcar0 = hv.x; hcar1 = hv.y; }
    float4 xgA = *(const float4*)(g_X + ((size_t)gA * TBROWS) * DH + mE * DH + nAe);

    for (int t = 0; t < T_STEPS; t++) {
        // ---------------- PHASE A (u, r) ----------------
        float4 hvA = *(const float4*)(g_h + mE * DH + nAe);

        float acc[4][2][4];
#pragma unroll
        for (int mf = 0; mf < 4; mf++)
#pragma unroll
            for (int nf = 0; nf < 2; nf++)
#pragma unroll
                for (int e = 0; e < 4; e++) acc[mf][nf][e] = 0.f;

#pragma unroll
        for (int j = 0; j < 8; j++) {
            const int kb = wid * 8 + j;
            const uint4* ph = (const uint4*)(g_hfh + (size_t)kb * 512);
            const uint4* pl = (const uint4*)(g_hfl + (size_t)kb * 512);
            uint4 ah4[4], al4[4];
#pragma unroll
            for (int mf = 0; mf < 4; mf++) {
                ah4[mf] = ph[mf * 32 + lane];
                al4[mf] = pl[mf * 32 + lane];
            }
#pragma unroll
            for (int mf = 0; mf < 4; mf++) {
                uint32_t ah[4] = {ah4[mf].x, ah4[mf].y, ah4[mf].z, ah4[mf].w};
                uint32_t al[4] = {al4[mf].x, al4[mf].y, al4[mf].z, al4[mf].w};
                MMA_BF16(acc[mf][0], ah, wAh0[j]);
                MMA_BF16(acc[mf][0], ah, wAl0[j]);
                MMA_BF16(acc[mf][0], al, wAh0[j]);
                MMA_BF16(acc[mf][1], ah, wAh1[j]);
                MMA_BF16(acc[mf][1], ah, wAl1[j]);
                MMA_BF16(acc[mf][1], al, wAh1[j]);
            }
        }

        {
            float* rw = red + wid * 1536;
#pragma unroll
            for (int mf = 0; mf < 4; mf++)
#pragma unroll
                for (int nf = 0; nf < 2; nf++) {
                    int row = mf * 16 + (lane >> 2);
                    int col = nf * 8 + (lane & 3) * 2;
                    *(float2*)&rw[row * 20 + col] =
                        make_float2(acc[mf][nf][0], acc[mf][nf][1]);
                    *(float2*)&rw[(row + 8) * 20 + col] =
                        make_float2(acc[mf][nf][2], acc[mf][nf][3]);
                }
        }
        __syncthreads();
        {
            float4 sv = make_float4(0.f, 0.f, 0.f, 0.f);
#pragma unroll
            for (int w = 0; w < 8; w++) {
                float4 v = *(float4*)&red[w * 1536 + mE * 20 + cbA];
                sv.x += v.x; sv.y += v.y; sv.z += v.z; sv.w += v.w;
            }
            float s0 = 1.f / (1.f + expf(-(sv.x + xgA.x)));
            float s1 = 1.f / (1.f + expf(-(sv.y + xgA.y)));
            float s2 = 1.f / (1.f + expf(-(sv.z + xgA.z)));
            float s3 = 1.f / (1.f + expf(-(sv.w + xgA.w)));
            if (gA == 0) {
                *(float4*)&g_u[mE * DH + nAe] = make_float4(s0, s1, s2, s3);
            } else {
                float r0f = s0 * hvA.x, r1f = s1 * hvA.y;
                float r2f = s2 * hvA.z, r3f = s3 * hvA.w;
                uint32_t h01, l01, h23, l23;
                split2(r0f, r1f, h01, l01);
                split2(r2f, r3f, h23, l23);
                uint32_t f0 = frag_word(mE, nAe), f1 = frag_word(mE, nAe + 2);
                g_rfh[f0] = h01; g_rfh[f1] = h23;
                g_rfl[f0] = l01; g_rfl[f1] = l23;
            }
        }
        float2 xcB = *(const float2*)(g_X + (2ull * TBROWS
                          + (size_t)t * B_SZ) * DH + mE * DH + nBe);
        grid_barrier(lgen);

        // ---------------- PHASE B (candidate + update) ----------------
        float2 uvB = *(const float2*)(g_u + mE * DH + nBe);

        float accB[4][4];
#pragma unroll
        for (int mf = 0; mf < 4; mf++)
#pragma unroll
            for (int e = 0; e < 4; e++) accB[mf][e] = 0.f;

#pragma unroll
        for (int j = 0; j < 8; j++) {
            const int kb = wid * 8 + j;
            const uint4* ph = (const uint4*)(g_rfh + (size_t)kb * 512);
            const uint4* pl = (const uint4*)(g_rfl + (size_t)kb * 512);
            uint4 ah4[4], al4[4];
#pragma unroll
            for (int mf = 0; mf < 4; mf++) {
                ah4[mf] = ph[mf * 32 + lane];
                al4[mf] = pl[mf * 32 + lane];
            }
#pragma unroll
            for (int mf = 0; mf < 4; mf++) {
                uint32_t ah[4] = {ah4[mf].x, ah4[mf].y, ah4[mf].z, ah4[mf].w};
                uint32_t al[4] = {al4[mf].x, al4[mf].y, al4[mf].z, al4[mf].w};
                MMA_BF16(accB[mf], ah, wBh[j]);
                MMA_BF16(accB[mf], ah, wBl[j]);
                MMA_BF16(accB[mf], al, wBh[j]);
            }
        }

        {
            float* rw = red + wid * 1536;
#pragma unroll
            for (int mf = 0; mf < 4; mf++) {
                int row = mf * 16 + (lane >> 2);
                int col = (lane & 3) * 2;
                *(float2*)&rw[row * 10 + col] =
                    make_float2(accB[mf][0], accB[mf][1]);
                *(float2*)&rw[(row + 8) * 10 + col] =
                    make_float2(accB[mf][2], accB[mf][3]);
            }
        }
        __syncthreads();
        {
            float2 sv = make_float2(0.f, 0.f);
#pragma unroll
            for (int w = 0; w < 8; w++) {
                float2 v = *(float2*)&red[w * 1536 + mE * 10 + cbB];
                sv.x += v.x; sv.y += v.y;
            }
            float c0 = tanhf(sv.x + xcB.x);
            float c1 = tanhf(sv.y + xcB.y);
            float hn0 = (1.f - uvB.x) * hcar0 + uvB.x * c0;
            float hn1 = (1.f - uvB.y) * hcar1 + uvB.y * c1;
            hcar0 = hn0; hcar1 = hn1;
            *(float2*)&g_h[mE * DH + nBe] = make_float2(hn0, hn1);
            uint32_t hw, lw; split2(hn0, hn1, hw, lw);
            uint32_t f = frag_word(mE, nBe);
            g_hfh[f] = hw; g_hfl[f] = lw;
            size_t ob = ((size_t)t * B_SZ + mE) * DH + nBe;
            *(float2*)&out[ob] = make_float2(hn0, hn1);
            if (write_tail && t == T_STEPS - 1) {
                size_t tb = ((size_t)T_STEPS * B_SZ + mE) * DH + nBe;
                *(float2*)&out[tb] = make_float2(hn0, hn1);
            }
        }
        if (t + 1 < T_STEPS) {
            xgA = *(const float4*)(g_X + ((size_t)gA * TBROWS
                      + (size_t)(t + 1) * B_SZ) * DH + mE * DH + nAe);
        }
        grid_barrier(lgen);
    }
}

// ============================================================================
// Launch: 3 kernels per call
// ============================================================================
extern "C" void kernel_launch(void* const* d_in, const int* in_sizes, int n_in,
                              void* d_out, int out_size) {
    const float* emb    = (const float*)d_in[0];
    const float* hx     = (const float*)d_in[1];
    const float* w_ih_u = (const float*)d_in[2];
    const float* w_ih_r = (const float*)d_in[3];
    const float* w_ih_c = (const float*)d_in[4];
    const float* w_hh_u = (const float*)d_in[5];
    const float* w_hh_r = (const float*)d_in[6];
    const float* w_hh_c = (const float*)d_in[7];
    const float* b_u    = (const float*)d_in[8];
    const float* b_r    = (const float*)d_in[9];
    const float* b_c    = (const float*)d_in[10];
    float* out = (float*)d_out;

    const long long main_elems = (long long)T_STEPS * B_SZ * DH;
    int write_tail = ((long long)out_size >= main_elems + (long long)B_SZ * DH) ? 1 : 0;

    cudaFuncSetAttribute(gemm_input_tc,
                         cudaFuncAttributeMaxDynamicSharedMemorySize, GEMM_SM);
    cudaFuncSetAttribute(gru_pers_tc,
                         cudaFuncAttributeMaxDynamicSharedMemorySize, PERS_SM);

    int prep_blocks = (int)((PREP_TOT + 255) / 256);
    prep_all<<<prep_blocks, 256>>>(emb, w_ih_u, w_ih_r, w_ih_c, hx);

    dim3 g1(DH / 128, TBROWS / 128, 3);
    gemm_input_tc<<<g1, 256, GEMM_SM>>>(b_u, b_r, b_c);
    gru_pers_tc<<<NBLK, NTHR, PERS_SM>>>(w_hh_u, w_hh_r, w_hh_c, out, write_tail);
}